// round 16
// baseline (speedup 1.0000x reference)
#include <cuda_runtime.h>
#include <cuda_bf16.h>
#include <cstdint>

// ---------------------------------------------------------------------------
// QuantumFeedForwardBlock: 8-wire statevector sim (1 warp/token) + MLP GEMM
// Inputs (metadata order): x[4,4096,512] f32, ry_theta[8], rand_params[20],
//                          W1[64,8], b1[64], W2[512,64], b2[512]
// Output: f32 [4,4096,512]
// R15: compile-time OPTIMAL wire->bit permutation (3 hottest wires become
//      register bits -> fewer shuffle gates), WHT-based Z-expectation
//      reduction, dead-shuffle removal in reg-controlled CNOT, qsim split
//      into 4 launches (ncu observability). mlp2 (split-bf16 HMMA) unchanged.
// ---------------------------------------------------------------------------

#define NOPS 20
#define MAXTOK 16384

__device__ __nv_bfloat16 g_A[MAXTOK * 128];   // [m][0:64]=hi(h), [64:128]=lo(h)

struct Ops { int kind[NOPS]; int a[NOPS]; int b[NOPS]; };

// ---------------- constexpr numpy-legacy MT19937 ---------------------------
struct MTState { uint32_t mt[624]; int mti; };

__host__ __device__ constexpr void mt_seed(MTState& s, uint32_t seed) {
    s.mt[0] = seed;
    for (int i = 1; i < 624; i++)
        s.mt[i] = 1812433253u * (s.mt[i-1] ^ (s.mt[i-1] >> 30)) + (uint32_t)i;
    s.mti = 624;
}
__host__ __device__ constexpr uint32_t mt_next(MTState& s) {
    if (s.mti >= 624) {
        for (int i = 0; i < 624; i++) {
            uint32_t y = (s.mt[i] & 0x80000000u) | (s.mt[(i+1)%624] & 0x7fffffffu);
            uint32_t v = s.mt[(i+397)%624] ^ (y >> 1);
            if (y & 1u) v ^= 0x9908b0dfu;
            s.mt[i] = v;
        }
        s.mti = 0;
    }
    uint32_t y = s.mt[s.mti++];
    y ^= y >> 11;
    y ^= (y << 7)  & 0x9d2c5680u;
    y ^= (y << 15) & 0xefc60000u;
    y ^= y >> 18;
    return y;
}
__host__ __device__ constexpr uint32_t mt_bounded(MTState& s, uint32_t maxv) {
    uint32_t mask = maxv;
    mask |= mask >> 1; mask |= mask >> 2; mask |= mask >> 4;
    mask |= mask >> 8; mask |= mask >> 16;
    uint32_t v = mt_next(s) & mask;
    while (v > maxv) v = mt_next(s) & mask;
    return v;
}
__host__ __device__ constexpr Ops build_ops_ce() {
    Ops ops{};
    MTState st{};
    mt_seed(st, 0u);
    for (int i = 0; i < NOPS; i++) {
        uint32_t k = mt_bounded(st, 3u);               // randint(4)
        if (k == 3u) {                                  // cnot: choice(8,2,False)
            int perm[8] = {0,1,2,3,4,5,6,7};
            for (int ii = 7; ii >= 1; ii--) {           // legacy Fisher-Yates
                uint32_t j = mt_bounded(st, (uint32_t)ii);
                int t = perm[ii]; perm[ii] = perm[j]; perm[j] = t;
            }
            ops.kind[i] = 3; ops.a[i] = perm[0]; ops.b[i] = perm[1];
        } else {
            uint32_t w = mt_bounded(st, 7u);            // randint(8)
            ops.kind[i] = (int)k; ops.a[i] = (int)w; ops.b[i] = 0;
        }
    }
    return ops;
}
__host__ __device__ constexpr int op_kind(int g) { return build_ops_ce().kind[g]; }
__host__ __device__ constexpr int op_a(int g)    { return build_ops_ce().a[g]; }
__host__ __device__ constexpr int op_b(int g)    { return build_ops_ce().b[g]; }

// ---------------- compile-time wire -> bit-position permutation ------------
// pos[w] in 0..2  -> register bit (shuffle-free gates)
// pos[w] in 3..7  -> lane bit (pos-3) (gates need warp shuffles)
// Greedy: 3 highest-shuffle-cost wires get register bits.
struct PosMap { int pos[8]; };
__host__ __device__ constexpr PosMap compute_pos() {
    Ops ops = build_ops_ce();
    int score[8] = {16,16,16,16,16,16,16,16};           // final RY layer
    for (int i = 0; i < NOPS; i++) {
        if (ops.kind[i] == 3) { score[ops.b[i]] += 14; score[ops.a[i]] += 1; }
        else if (ops.kind[i] != 2) score[ops.a[i]] += 16;   // rx/ry cost SHFL
    }
    PosMap pm{};
    bool used[8] = {};
    for (int b = 0; b < 3; b++) {
        int best = 0, bs = -1;
        for (int w = 0; w < 8; w++)
            if (!used[w] && score[w] > bs) { bs = score[w]; best = w; }
        used[best] = true;
        pm.pos[best] = b;
    }
    int nb = 3;
    for (int w = 0; w < 8; w++) if (!used[w]) { pm.pos[w] = nb; nb++; }
    return pm;
}
__host__ __device__ constexpr int wposf(int w) { return compute_pos().pos[w]; }

// ---------------- device helpers -------------------------------------------
__device__ __forceinline__ double cpack(float r, float i) {
    return __hiloint2double(__float_as_int(i), __float_as_int(r));
}
__device__ __forceinline__ void cunpack(double d, float& r, float& i) {
    r = __int_as_float(__double2loint(d));
    i = __int_as_float(__double2hiint(d));
}
__device__ __forceinline__ uint32_t smem_u32(const void* p) {
    return (uint32_t)__cvta_generic_to_shared(p);
}
__device__ __forceinline__ void ldsm4(uint32_t* r, uint32_t addr) {
    asm volatile("ldmatrix.sync.aligned.m8n8.x4.shared.b16 {%0,%1,%2,%3}, [%4];"
        : "=r"(r[0]), "=r"(r[1]), "=r"(r[2]), "=r"(r[3]) : "r"(addr));
}
__device__ __forceinline__ void ldsm2(uint32_t* r, uint32_t addr) {
    asm volatile("ldmatrix.sync.aligned.m8n8.x2.shared.b16 {%0,%1}, [%2];"
        : "=r"(r[0]), "=r"(r[1]) : "r"(addr));
}
__device__ __forceinline__ void mma_bf16(float* c, const uint32_t* a,
                                         const uint32_t* b) {
    asm volatile(
        "mma.sync.aligned.m16n8k16.row.col.f32.bf16.bf16.f32 "
        "{%0,%1,%2,%3}, {%4,%5,%6,%7}, {%8,%9}, {%0,%1,%2,%3};"
        : "+f"(c[0]), "+f"(c[1]), "+f"(c[2]), "+f"(c[3])
        : "r"(a[0]), "r"(a[1]), "r"(a[2]), "r"(a[3]), "r"(b[0]), "r"(b[1]));
}

// ---- gate helpers (positions/masks as template parameters) ----------------
template<int M>
__device__ __forceinline__ void rx_lane(float (&re)[8], float (&im)[8],
                                        float c, float s) {
#pragma unroll
    for (int r = 0; r < 8; r++) {
        double d = __shfl_xor_sync(0xffffffffu, cpack(re[r], im[r]), M);
        float pr, pi; cunpack(d, pr, pi);
        float nr = c * re[r] + s * pi;
        float ni = c * im[r] - s * pr;
        re[r] = nr; im[r] = ni;
    }
}
template<int M>
__device__ __forceinline__ void ry_lane(float (&re)[8], float (&im)[8],
                                        float c, float s, int lane) {
    float ss = (lane & M) ? s : -s;
#pragma unroll
    for (int r = 0; r < 8; r++) {
        double d = __shfl_xor_sync(0xffffffffu, cpack(re[r], im[r]), M);
        float pr, pi; cunpack(d, pr, pi);
        re[r] = c * re[r] + ss * pr;
        im[r] = c * im[r] + ss * pi;
    }
}
template<int P>
__device__ __forceinline__ void rz_g(float (&re)[8], float (&im)[8],
                                     float c, float s, int lane) {
    if constexpr (P >= 3) {
        float se = ((lane >> (P - 3)) & 1) ? s : -s;
#pragma unroll
        for (int r = 0; r < 8; r++) {
            float nr = c * re[r] - se * im[r];
            float ni = c * im[r] + se * re[r];
            re[r] = nr; im[r] = ni;
        }
    } else {
#pragma unroll
        for (int r = 0; r < 8; r++) {
            const float se = ((r >> P) & 1) ? s : -s;   // compile-time sign
            float nr = c * re[r] - se * im[r];
            float ni = c * im[r] + se * re[r];
            re[r] = nr; im[r] = ni;
        }
    }
}
template<int TM>
__device__ __forceinline__ void rx_reg(float (&re)[8], float (&im)[8],
                                       float c, float s) {
#pragma unroll
    for (int r = 0; r < 8; r++) {
        if (r & TM) continue;
        const int q = r | TM;
        float ar = re[r], ai = im[r], br = re[q], bi = im[q];
        re[r] = c*ar + s*bi;  im[r] = c*ai - s*br;
        re[q] = c*br + s*ai;  im[q] = c*bi - s*ar;
    }
}
template<int TM>
__device__ __forceinline__ void ry_reg(float (&re)[8], float (&im)[8],
                                       float c, float s) {
#pragma unroll
    for (int r = 0; r < 8; r++) {
        if (r & TM) continue;
        const int q = r | TM;
        float ar = re[r], ai = im[r], br = re[q], bi = im[q];
        re[r] = c*ar - s*br;  im[r] = c*ai - s*bi;
        re[q] = s*ar + c*br;  im[q] = s*ai + c*bi;
    }
}
template<int TM, int CP>
__device__ __forceinline__ void cnot_rt(float (&re)[8], float (&im)[8], int lane) {
    if constexpr (CP >= 3) {
        bool cb = ((lane >> (CP - 3)) & 1) != 0;
#pragma unroll
        for (int r = 0; r < 8; r++) {
            if (r & TM) continue;
            const int q = r | TM;
            float ar = re[r], ai = im[r], br = re[q], bi = im[q];
            re[r] = cb ? br : ar;  im[r] = cb ? bi : ai;
            re[q] = cb ? ar : br;  im[q] = cb ? ai : bi;
        }
    } else {
        // control bit lives in r: compile-time swap (pure register rename)
#pragma unroll
        for (int r = 0; r < 8; r++) {
            if ((r & TM) == 0 && ((r >> CP) & 1)) {
                const int q = r | TM;
                float t;
                t = re[r]; re[r] = re[q]; re[q] = t;
                t = im[r]; im[r] = im[q]; im[q] = t;
            }
        }
    }
}
template<int M, int CP>
__device__ __forceinline__ void cnot_lt(float (&re)[8], float (&im)[8], int lane) {
    if constexpr (CP >= 3) {
        bool cb = ((lane >> (CP - 3)) & 1) != 0;
#pragma unroll
        for (int r = 0; r < 8; r++) {
            double d = __shfl_xor_sync(0xffffffffu, cpack(re[r], im[r]), M);
            float pr, pi; cunpack(d, pr, pi);
            re[r] = cb ? pr : re[r];
            im[r] = cb ? pi : im[r];
        }
    } else {
        // reg-bit control: condition on r is compile-time uniform across
        // lanes -> shuffle ONLY the registers that move (no dummy shuffles)
#pragma unroll
        for (int r = 0; r < 8; r++) {
            if ((r >> CP) & 1) {
                double d = __shfl_xor_sync(0xffffffffu, cpack(re[r], im[r]), M);
                cunpack(d, re[r], im[r]);
            }
        }
    }
}

// ---- compile-time gate dispatcher -----------------------------------------
template<int G>
__device__ __forceinline__ void do_gate(float (&re)[8], float (&im)[8],
                                        const float* __restrict__ gc,
                                        const float* __restrict__ gs, int lane) {
    if constexpr (G >= NOPS) {                       // final RY layer, wire G-20
        constexpr int p = wposf(G - NOPS);
        const float c = gc[G], s = gs[G];
        if constexpr (p >= 3) ry_lane<(1 << (p - 3))>(re, im, c, s, lane);
        else                  ry_reg<(1 << p)>(re, im, c, s);
    } else {
        constexpr int kind = op_kind(G);
        constexpr int wa = op_a(G);
        constexpr int wb = op_b(G);
        if constexpr (kind == 3) {
            constexpr int cp = wposf(wa);
            constexpr int tp = wposf(wb);
            if constexpr (tp >= 3) cnot_lt<(1 << (tp - 3)), cp>(re, im, lane);
            else                   cnot_rt<(1 << tp), cp>(re, im, lane);
        } else if constexpr (kind == 2) {
            rz_g<wposf(wa)>(re, im, gc[G], gs[G], lane);
        } else if constexpr (kind == 0) {
            constexpr int p = wposf(wa);
            const float c = gc[G], s = gs[G];
            if constexpr (p >= 3) rx_lane<(1 << (p - 3))>(re, im, c, s);
            else                  rx_reg<(1 << p)>(re, im, c, s);
        } else {
            constexpr int p = wposf(wa);
            const float c = gc[G], s = gs[G];
            if constexpr (p >= 3) ry_lane<(1 << (p - 3))>(re, im, c, s, lane);
            else                  ry_reg<(1 << p)>(re, im, c, s);
        }
    }
}
template<int G>
__device__ __forceinline__ void run_gates(float (&re)[8], float (&im)[8],
                                          const float* __restrict__ gc,
                                          const float* __restrict__ gs, int lane) {
    if constexpr (G < 28) {
        do_gate<G>(re, im, gc, gs, lane);
        run_gates<G + 1>(re, im, gc, gs, lane);
    }
}

// ---- init-state builders under the permutation ----------------------------
template<int W>
__device__ __forceinline__ float lane_init(const float* cw, const float* sw,
                                           int lane) {
    if constexpr (W == 8) return 1.f;
    else {
        float f = lane_init<W + 1>(cw, sw, lane);
        constexpr int P = wposf(W);
        if constexpr (P >= 3)
            f *= ((lane >> (P - 3)) & 1) ? sw[W] : cw[W];
        return f;
    }
}
template<int R, int W>
__device__ __forceinline__ float reg_init(const float* cw, const float* sw) {
    if constexpr (W == 8) return 1.f;
    else {
        float f = reg_init<R, W + 1>(cw, sw);
        constexpr int P = wposf(W);
        if constexpr (P < 3)
            f *= ((R >> P) & 1) ? sw[W] : cw[W];
        return f;
    }
}
template<int R>
__device__ __forceinline__ void set_init(float (&re)[8], float (&im)[8],
                                         float lf, const float* cw,
                                         const float* sw) {
    if constexpr (R < 8) {
        re[R] = lf * reg_init<R, 0>(cw, sw);
        im[R] = 0.f;
        set_init<R + 1>(re, im, lf, cw, sw);
    }
}
// ---- ev extraction under the permutation ----------------------------------
template<int W>
__device__ __forceinline__ void fill_ev(float (&ev)[8], float wht,
                                        const float (&E)[3]) {
    if constexpr (W < 8) {
        constexpr int P = wposf(W);
        if constexpr (P >= 3)
            ev[W] = __shfl_sync(0xffffffffu, wht, 1 << (P - 3));
        else
            ev[W] = E[P];
        fill_ev<W + 1>(ev, wht, E);
    }
}

// ---------------- kernel 1: statevector sim + MLP layer 1 ------------------
__global__ __launch_bounds__(256)
void qsim_kernel(const float* __restrict__ x,
                 const float* __restrict__ ry_theta,
                 const float* __restrict__ rand_params,
                 const float* __restrict__ W1,
                 const float* __restrict__ b1,
                 int token_base)
{
    __shared__ float gc[28], gs[28];
    __shared__ float W1t[8 * 64];
    __shared__ float b1s[64];
    __shared__ float Hs[64][9];           // pad 9: conflict-free scatter

    const int tid = threadIdx.x;
    if (tid < 28) {
        float th = (tid < 20) ? rand_params[tid] : ry_theta[tid - 20];
        float s, c;
        sincosf(0.5f * th, &s, &c);
        gc[tid] = c;
        gs[tid] = s;                      // CNOT slots unused by do_gate
    }
    if (tid < 64) b1s[tid] = b1[tid];
    for (int i = tid; i < 512; i += 256) {
        int j = i >> 3, w = i & 7;
        W1t[w * 64 + j] = W1[i];
    }
    __syncthreads();

    const int lane  = tid & 31;
    const int wid   = tid >> 5;
    const int token0 = token_base + blockIdx.x * 8;
    const int token  = token0 + wid;

    // ---- initial product state from the 8 input features ----
    const float* xf = x + (size_t)token * 512;
    float cw[8], sw[8];
#pragma unroll
    for (int w = 0; w < 8; w++) {
        float f = __ldg(xf + w);
        __sincosf(0.5f * f, &sw[w], &cw[w]);
    }
    float re[8], im[8];
    {
        const float lf = lane_init<0>(cw, sw, lane);
        set_init<0>(re, im, lf, cw, sw);
    }

    // ---- 20 random gates + 8 final RY gates (fully unrolled) ----
    run_gates<0>(re, im, gc, gs, lane);

    // ---- probs -> per-lane partials ----
    float S = 0.f;
    float E[3] = {0.f, 0.f, 0.f};
#pragma unroll
    for (int r = 0; r < 8; r++) {
        float p = re[r] * re[r] + im[r] * im[r];
        S += p;
        E[0] += (r & 1) ? -p : p;
        E[1] += (r & 2) ? -p : p;
        E[2] += (r & 4) ? -p : p;
    }
    // Walsh-Hadamard over lanes: lane j ends with F(j)=sum_i (-1)^{pc(i&j)} S_i
    float wht = S;
#pragma unroll
    for (int m = 16; m >= 1; m >>= 1) {
        float t = __shfl_xor_sync(0xffffffffu, wht, m);
        wht = (lane & m) ? (t - wht) : (t + wht);
    }
    // plain butterflies for the 3 register-bit expectations
#pragma unroll
    for (int e = 0; e < 3; e++) {
        float v = E[e];
#pragma unroll
        for (int m = 16; m >= 1; m >>= 1) v += __shfl_xor_sync(0xffffffffu, v, m);
        E[e] = v;
    }
    float ev[8];
    fill_ev<0>(ev, wht, E);

    // ---- MLP layer 1: h = relu(ev @ W1^T + b1), staged to smem ----
#pragma unroll
    for (int half = 0; half < 2; half++) {
        const int j = lane + half * 32;
        float acc = b1s[j];
#pragma unroll
        for (int w = 0; w < 8; w++) acc = fmaf(ev[w], W1t[w * 64 + j], acc);
        Hs[j][wid] = fmaxf(acc, 0.f);
    }
    __syncthreads();

    // ---- bf16 hi/lo split writeout: g_A[m][0:64]=hi, [64:128]=lo ----
#pragma unroll
    for (int it = 0; it < 2; it++) {
        const int idx = it * 256 + tid;           // 512 h-values per block
        const int tok = idx >> 6, j = idx & 63;
        float h = Hs[j][tok];
        __nv_bfloat16 hi = __float2bfloat16(h);
        __nv_bfloat16 lo = __float2bfloat16(h - __bfloat162float(hi));
        __nv_bfloat16* row = g_A + (size_t)(token0 + tok) * 128;
        row[j]      = hi;
        row[64 + j] = lo;
    }
}

// ---------------- kernel 2: out = H @ W2^T + b2  (split-bf16 HMMA) ---------
// M=16384, N=512, K=64 fp32 ->  bf16 hi/lo, 3 K-block products:
//   blk0: A=hi, B=whi   blk1: A=lo, B=whi   blk2: A=hi, B=wlo
// BM=128, BN=64, 256 threads (8 warps as 4m x 2n, each warp 32m x 32n).
#define PITCH 272   // smem row pitch in bytes (136 bf16): conflict-free ldmatrix
__global__ __launch_bounds__(256)
void mlp2_kernel(const float* __restrict__ W2,
                 const float* __restrict__ b2,
                 float* __restrict__ out)
{
    extern __shared__ char smem[];
    char* As = smem;                  // [128 rows][PITCH]  bf16 (hi|lo)
    char* Bs = smem + 128 * PITCH;    // [64 rows][PITCH]   bf16 (whi|wlo)

    const int tid = threadIdx.x;
    const int m0 = blockIdx.y * 128;
    const int n0 = blockIdx.x * 64;

    // ---- load A tile (bf16, 128 rows x 256B) ----
#pragma unroll
    for (int it = 0; it < 8; it++) {
        const int c = it * 256 + tid;             // 2048 x 16B chunks
        const int row = c >> 4, ch = c & 15;
        uint4 v = *(const uint4*)((const char*)g_A + (size_t)(m0 + row) * 256 + ch * 16);
        *(uint4*)(As + row * PITCH + ch * 16) = v;
    }
    // ---- load W2 tile (f32) and split to bf16 hi|lo in smem ----
#pragma unroll
    for (int it = 0; it < 8; it++) {
        const int c = it * 256 + tid;             // 2048 x float2
        const int n = c >> 5, kk = c & 31;        // k pair index
        float2 v = *(const float2*)(W2 + (size_t)(n0 + n) * 64 + kk * 2);
        __nv_bfloat16 h0 = __float2bfloat16(v.x);
        __nv_bfloat16 h1 = __float2bfloat16(v.y);
        __nv_bfloat16 l0 = __float2bfloat16(v.x - __bfloat162float(h0));
        __nv_bfloat16 l1 = __float2bfloat16(v.y - __bfloat162float(h1));
        *(__nv_bfloat162*)(Bs + n * PITCH + kk * 4)       = __nv_bfloat162(h0, h1);
        *(__nv_bfloat162*)(Bs + n * PITCH + 128 + kk * 4) = __nv_bfloat162(l0, l1);
    }
    __syncthreads();

    const int lane = tid & 31;
    const int wid  = tid >> 5;
    const int wm = (wid & 3) * 32;    // warp m-origin within tile
    const int wn = (wid >> 2) * 32;   // warp n-origin within tile

    const uint32_t aBase = smem_u32(As);
    const uint32_t bBase = smem_u32(Bs);
    uint32_t aRow[2], bRow[4];
#pragma unroll
    for (int mt = 0; mt < 2; mt++)
        aRow[mt] = aBase + (wm + mt * 16 + (lane & 15)) * PITCH + (lane >> 4) * 16;
#pragma unroll
    for (int nt = 0; nt < 4; nt++)
        bRow[nt] = bBase + (wn + nt * 8 + (lane & 7)) * PITCH + ((lane >> 3) & 1) * 16;

    float acc[2][4][4];
#pragma unroll
    for (int mt = 0; mt < 2; mt++)
#pragma unroll
        for (int nt = 0; nt < 4; nt++)
#pragma unroll
            for (int i = 0; i < 4; i++) acc[mt][nt][i] = 0.f;

#pragma unroll
    for (int blk = 0; blk < 3; blk++) {
        const int ka = (blk == 1) ? 128 : 0;      // A byte offset: hi,lo,hi
        const int kb = (blk == 2) ? 128 : 0;      // B byte offset: whi,whi,wlo
#pragma unroll
        for (int ks = 0; ks < 4; ks++) {
            const int koa = ka + ks * 32;          // 16 bf16 = 32 bytes
            const int kob = kb + ks * 32;
            uint32_t a[2][4], b[4][2];
#pragma unroll
            for (int mt = 0; mt < 2; mt++) ldsm4(a[mt], aRow[mt] + koa);
#pragma unroll
            for (int nt = 0; nt < 4; nt++) ldsm2(b[nt], bRow[nt] + kob);
#pragma unroll
            for (int mt = 0; mt < 2; mt++)
#pragma unroll
                for (int nt = 0; nt < 4; nt++)
                    mma_bf16(acc[mt][nt], a[mt], b[nt]);
        }
    }

    // ---- epilogue: add bias, write fp32 ----
#pragma unroll
    for (int nt = 0; nt < 4; nt++) {
        const int n = n0 + wn + nt * 8 + (lane & 3) * 2;
        const float2 bb = *(const float2*)(b2 + n);
#pragma unroll
        for (int mt = 0; mt < 2; mt++) {
            const int r0 = m0 + wm + mt * 16 + (lane >> 2);
            const float* c = acc[mt][nt];
            float2 o0 = {c[0] + bb.x, c[1] + bb.y};
            float2 o1 = {c[2] + bb.x, c[3] + bb.y};
            *(float2*)(out + (size_t)r0 * 512 + n)       = o0;
            *(float2*)(out + (size_t)(r0 + 8) * 512 + n) = o1;
        }
    }
}

// ---------------- entry point ----------------------------------------------
extern "C" void kernel_launch(void* const* d_in, const int* in_sizes, int n_in,
                              void* d_out, int out_size)
{
    const float* x  = (const float*)d_in[0];
    const float* ry = (const float*)d_in[1];
    const float* rp = (const float*)d_in[2];
    const float* W1 = (const float*)d_in[3];
    const float* b1 = (const float*)d_in[4];
    const float* W2 = (const float*)d_in[5];
    const float* b2 = (const float*)d_in[6];
    float* out = (float*)d_out;

    const int tokens = in_sizes[0] / 512;      // 16384
    const int quarter = tokens / 4;            // 4096 tokens per launch

    // 4 launches: same total work; puts a qsim launch at ncu's -s 5 -c 1 slot
    for (int q = 0; q < 4; q++)
        qsim_kernel<<<quarter / 8, 256>>>(x, ry, rp, W1, b1, q * quarter);

    const int smem2 = (128 + 64) * PITCH;      // 52224 B
    cudaFuncSetAttribute(mlp2_kernel,
                         cudaFuncAttributeMaxDynamicSharedMemorySize, smem2);
    dim3 g2(512 / 64, tokens / 128);
    mlp2_kernel<<<g2, 256, smem2>>>(W2, b2, out);
}

// round 17
// speedup vs baseline: 1.2342x; 1.2342x over previous
#include <cuda_runtime.h>
#include <cuda_bf16.h>
#include <cstdint>

// ---------------------------------------------------------------------------
// QuantumFeedForwardBlock: 8-wire statevector sim (1 warp/token) + MLP GEMM
// Inputs (metadata order): x[4,4096,512] f32, ry_theta[8], rand_params[20],
//                          W1[64,8], b1[64], W2[512,64], b2[512]
// Output: f32 [4,4096,512]
// R17: single qsim launch restored (R15's 4-way split capped occupancy at
//      grid/148 -> 43% and added 4x launch tails). All R15 content kept:
//      compile-time wire->bit permutation, WHT reduction, dead-shuffle-free
//      CNOT. mlp2 (split-bf16 HMMA) unchanged.
// ---------------------------------------------------------------------------

#define NOPS 20
#define MAXTOK 16384

__device__ __nv_bfloat16 g_A[MAXTOK * 128];   // [m][0:64]=hi(h), [64:128]=lo(h)

struct Ops { int kind[NOPS]; int a[NOPS]; int b[NOPS]; };

// ---------------- constexpr numpy-legacy MT19937 ---------------------------
struct MTState { uint32_t mt[624]; int mti; };

__host__ __device__ constexpr void mt_seed(MTState& s, uint32_t seed) {
    s.mt[0] = seed;
    for (int i = 1; i < 624; i++)
        s.mt[i] = 1812433253u * (s.mt[i-1] ^ (s.mt[i-1] >> 30)) + (uint32_t)i;
    s.mti = 624;
}
__host__ __device__ constexpr uint32_t mt_next(MTState& s) {
    if (s.mti >= 624) {
        for (int i = 0; i < 624; i++) {
            uint32_t y = (s.mt[i] & 0x80000000u) | (s.mt[(i+1)%624] & 0x7fffffffu);
            uint32_t v = s.mt[(i+397)%624] ^ (y >> 1);
            if (y & 1u) v ^= 0x9908b0dfu;
            s.mt[i] = v;
        }
        s.mti = 0;
    }
    uint32_t y = s.mt[s.mti++];
    y ^= y >> 11;
    y ^= (y << 7)  & 0x9d2c5680u;
    y ^= (y << 15) & 0xefc60000u;
    y ^= y >> 18;
    return y;
}
__host__ __device__ constexpr uint32_t mt_bounded(MTState& s, uint32_t maxv) {
    uint32_t mask = maxv;
    mask |= mask >> 1; mask |= mask >> 2; mask |= mask >> 4;
    mask |= mask >> 8; mask |= mask >> 16;
    uint32_t v = mt_next(s) & mask;
    while (v > maxv) v = mt_next(s) & mask;
    return v;
}
__host__ __device__ constexpr Ops build_ops_ce() {
    Ops ops{};
    MTState st{};
    mt_seed(st, 0u);
    for (int i = 0; i < NOPS; i++) {
        uint32_t k = mt_bounded(st, 3u);               // randint(4)
        if (k == 3u) {                                  // cnot: choice(8,2,False)
            int perm[8] = {0,1,2,3,4,5,6,7};
            for (int ii = 7; ii >= 1; ii--) {           // legacy Fisher-Yates
                uint32_t j = mt_bounded(st, (uint32_t)ii);
                int t = perm[ii]; perm[ii] = perm[j]; perm[j] = t;
            }
            ops.kind[i] = 3; ops.a[i] = perm[0]; ops.b[i] = perm[1];
        } else {
            uint32_t w = mt_bounded(st, 7u);            // randint(8)
            ops.kind[i] = (int)k; ops.a[i] = (int)w; ops.b[i] = 0;
        }
    }
    return ops;
}
__host__ __device__ constexpr int op_kind(int g) { return build_ops_ce().kind[g]; }
__host__ __device__ constexpr int op_a(int g)    { return build_ops_ce().a[g]; }
__host__ __device__ constexpr int op_b(int g)    { return build_ops_ce().b[g]; }

// ---------------- compile-time wire -> bit-position permutation ------------
// pos[w] in 0..2  -> register bit (shuffle-free gates)
// pos[w] in 3..7  -> lane bit (pos-3) (gates need warp shuffles)
// Greedy: 3 highest-shuffle-cost wires get register bits.
struct PosMap { int pos[8]; };
__host__ __device__ constexpr PosMap compute_pos() {
    Ops ops = build_ops_ce();
    int score[8] = {16,16,16,16,16,16,16,16};           // final RY layer
    for (int i = 0; i < NOPS; i++) {
        if (ops.kind[i] == 3) { score[ops.b[i]] += 14; score[ops.a[i]] += 1; }
        else if (ops.kind[i] != 2) score[ops.a[i]] += 16;   // rx/ry cost SHFL
    }
    PosMap pm{};
    bool used[8] = {};
    for (int b = 0; b < 3; b++) {
        int best = 0, bs = -1;
        for (int w = 0; w < 8; w++)
            if (!used[w] && score[w] > bs) { bs = score[w]; best = w; }
        used[best] = true;
        pm.pos[best] = b;
    }
    int nb = 3;
    for (int w = 0; w < 8; w++) if (!used[w]) { pm.pos[w] = nb; nb++; }
    return pm;
}
__host__ __device__ constexpr int wposf(int w) { return compute_pos().pos[w]; }

// ---------------- device helpers -------------------------------------------
__device__ __forceinline__ double cpack(float r, float i) {
    return __hiloint2double(__float_as_int(i), __float_as_int(r));
}
__device__ __forceinline__ void cunpack(double d, float& r, float& i) {
    r = __int_as_float(__double2loint(d));
    i = __int_as_float(__double2hiint(d));
}
__device__ __forceinline__ uint32_t smem_u32(const void* p) {
    return (uint32_t)__cvta_generic_to_shared(p);
}
__device__ __forceinline__ void ldsm4(uint32_t* r, uint32_t addr) {
    asm volatile("ldmatrix.sync.aligned.m8n8.x4.shared.b16 {%0,%1,%2,%3}, [%4];"
        : "=r"(r[0]), "=r"(r[1]), "=r"(r[2]), "=r"(r[3]) : "r"(addr));
}
__device__ __forceinline__ void ldsm2(uint32_t* r, uint32_t addr) {
    asm volatile("ldmatrix.sync.aligned.m8n8.x2.shared.b16 {%0,%1}, [%2];"
        : "=r"(r[0]), "=r"(r[1]) : "r"(addr));
}
__device__ __forceinline__ void mma_bf16(float* c, const uint32_t* a,
                                         const uint32_t* b) {
    asm volatile(
        "mma.sync.aligned.m16n8k16.row.col.f32.bf16.bf16.f32 "
        "{%0,%1,%2,%3}, {%4,%5,%6,%7}, {%8,%9}, {%0,%1,%2,%3};"
        : "+f"(c[0]), "+f"(c[1]), "+f"(c[2]), "+f"(c[3])
        : "r"(a[0]), "r"(a[1]), "r"(a[2]), "r"(a[3]), "r"(b[0]), "r"(b[1]));
}

// ---- gate helpers (positions/masks as template parameters) ----------------
template<int M>
__device__ __forceinline__ void rx_lane(float (&re)[8], float (&im)[8],
                                        float c, float s) {
#pragma unroll
    for (int r = 0; r < 8; r++) {
        double d = __shfl_xor_sync(0xffffffffu, cpack(re[r], im[r]), M);
        float pr, pi; cunpack(d, pr, pi);
        float nr = c * re[r] + s * pi;
        float ni = c * im[r] - s * pr;
        re[r] = nr; im[r] = ni;
    }
}
template<int M>
__device__ __forceinline__ void ry_lane(float (&re)[8], float (&im)[8],
                                        float c, float s, int lane) {
    float ss = (lane & M) ? s : -s;
#pragma unroll
    for (int r = 0; r < 8; r++) {
        double d = __shfl_xor_sync(0xffffffffu, cpack(re[r], im[r]), M);
        float pr, pi; cunpack(d, pr, pi);
        re[r] = c * re[r] + ss * pr;
        im[r] = c * im[r] + ss * pi;
    }
}
template<int P>
__device__ __forceinline__ void rz_g(float (&re)[8], float (&im)[8],
                                     float c, float s, int lane) {
    if constexpr (P >= 3) {
        float se = ((lane >> (P - 3)) & 1) ? s : -s;
#pragma unroll
        for (int r = 0; r < 8; r++) {
            float nr = c * re[r] - se * im[r];
            float ni = c * im[r] + se * re[r];
            re[r] = nr; im[r] = ni;
        }
    } else {
#pragma unroll
        for (int r = 0; r < 8; r++) {
            const float se = ((r >> P) & 1) ? s : -s;   // compile-time sign
            float nr = c * re[r] - se * im[r];
            float ni = c * im[r] + se * re[r];
            re[r] = nr; im[r] = ni;
        }
    }
}
template<int TM>
__device__ __forceinline__ void rx_reg(float (&re)[8], float (&im)[8],
                                       float c, float s) {
#pragma unroll
    for (int r = 0; r < 8; r++) {
        if (r & TM) continue;
        const int q = r | TM;
        float ar = re[r], ai = im[r], br = re[q], bi = im[q];
        re[r] = c*ar + s*bi;  im[r] = c*ai - s*br;
        re[q] = c*br + s*ai;  im[q] = c*bi - s*ar;
    }
}
template<int TM>
__device__ __forceinline__ void ry_reg(float (&re)[8], float (&im)[8],
                                       float c, float s) {
#pragma unroll
    for (int r = 0; r < 8; r++) {
        if (r & TM) continue;
        const int q = r | TM;
        float ar = re[r], ai = im[r], br = re[q], bi = im[q];
        re[r] = c*ar - s*br;  im[r] = c*ai - s*bi;
        re[q] = s*ar + c*br;  im[q] = s*ai + c*bi;
    }
}
template<int TM, int CP>
__device__ __forceinline__ void cnot_rt(float (&re)[8], float (&im)[8], int lane) {
    if constexpr (CP >= 3) {
        bool cb = ((lane >> (CP - 3)) & 1) != 0;
#pragma unroll
        for (int r = 0; r < 8; r++) {
            if (r & TM) continue;
            const int q = r | TM;
            float ar = re[r], ai = im[r], br = re[q], bi = im[q];
            re[r] = cb ? br : ar;  im[r] = cb ? bi : ai;
            re[q] = cb ? ar : br;  im[q] = cb ? ai : bi;
        }
    } else {
        // control bit lives in r: compile-time swap (pure register rename)
#pragma unroll
        for (int r = 0; r < 8; r++) {
            if ((r & TM) == 0 && ((r >> CP) & 1)) {
                const int q = r | TM;
                float t;
                t = re[r]; re[r] = re[q]; re[q] = t;
                t = im[r]; im[r] = im[q]; im[q] = t;
            }
        }
    }
}
template<int M, int CP>
__device__ __forceinline__ void cnot_lt(float (&re)[8], float (&im)[8], int lane) {
    if constexpr (CP >= 3) {
        bool cb = ((lane >> (CP - 3)) & 1) != 0;
#pragma unroll
        for (int r = 0; r < 8; r++) {
            double d = __shfl_xor_sync(0xffffffffu, cpack(re[r], im[r]), M);
            float pr, pi; cunpack(d, pr, pi);
            re[r] = cb ? pr : re[r];
            im[r] = cb ? pi : im[r];
        }
    } else {
        // reg-bit control: condition on r is compile-time uniform across
        // lanes -> shuffle ONLY the registers that move (no dummy shuffles)
#pragma unroll
        for (int r = 0; r < 8; r++) {
            if ((r >> CP) & 1) {
                double d = __shfl_xor_sync(0xffffffffu, cpack(re[r], im[r]), M);
                cunpack(d, re[r], im[r]);
            }
        }
    }
}

// ---- compile-time gate dispatcher -----------------------------------------
template<int G>
__device__ __forceinline__ void do_gate(float (&re)[8], float (&im)[8],
                                        const float* __restrict__ gc,
                                        const float* __restrict__ gs, int lane) {
    if constexpr (G >= NOPS) {                       // final RY layer, wire G-20
        constexpr int p = wposf(G - NOPS);
        const float c = gc[G], s = gs[G];
        if constexpr (p >= 3) ry_lane<(1 << (p - 3))>(re, im, c, s, lane);
        else                  ry_reg<(1 << p)>(re, im, c, s);
    } else {
        constexpr int kind = op_kind(G);
        constexpr int wa = op_a(G);
        constexpr int wb = op_b(G);
        if constexpr (kind == 3) {
            constexpr int cp = wposf(wa);
            constexpr int tp = wposf(wb);
            if constexpr (tp >= 3) cnot_lt<(1 << (tp - 3)), cp>(re, im, lane);
            else                   cnot_rt<(1 << tp), cp>(re, im, lane);
        } else if constexpr (kind == 2) {
            rz_g<wposf(wa)>(re, im, gc[G], gs[G], lane);
        } else if constexpr (kind == 0) {
            constexpr int p = wposf(wa);
            const float c = gc[G], s = gs[G];
            if constexpr (p >= 3) rx_lane<(1 << (p - 3))>(re, im, c, s);
            else                  rx_reg<(1 << p)>(re, im, c, s);
        } else {
            constexpr int p = wposf(wa);
            const float c = gc[G], s = gs[G];
            if constexpr (p >= 3) ry_lane<(1 << (p - 3))>(re, im, c, s, lane);
            else                  ry_reg<(1 << p)>(re, im, c, s);
        }
    }
}
template<int G>
__device__ __forceinline__ void run_gates(float (&re)[8], float (&im)[8],
                                          const float* __restrict__ gc,
                                          const float* __restrict__ gs, int lane) {
    if constexpr (G < 28) {
        do_gate<G>(re, im, gc, gs, lane);
        run_gates<G + 1>(re, im, gc, gs, lane);
    }
}

// ---- init-state builders under the permutation ----------------------------
template<int W>
__device__ __forceinline__ float lane_init(const float* cw, const float* sw,
                                           int lane) {
    if constexpr (W == 8) return 1.f;
    else {
        float f = lane_init<W + 1>(cw, sw, lane);
        constexpr int P = wposf(W);
        if constexpr (P >= 3)
            f *= ((lane >> (P - 3)) & 1) ? sw[W] : cw[W];
        return f;
    }
}
template<int R, int W>
__device__ __forceinline__ float reg_init(const float* cw, const float* sw) {
    if constexpr (W == 8) return 1.f;
    else {
        float f = reg_init<R, W + 1>(cw, sw);
        constexpr int P = wposf(W);
        if constexpr (P < 3)
            f *= ((R >> P) & 1) ? sw[W] : cw[W];
        return f;
    }
}
template<int R>
__device__ __forceinline__ void set_init(float (&re)[8], float (&im)[8],
                                         float lf, const float* cw,
                                         const float* sw) {
    if constexpr (R < 8) {
        re[R] = lf * reg_init<R, 0>(cw, sw);
        im[R] = 0.f;
        set_init<R + 1>(re, im, lf, cw, sw);
    }
}
// ---- ev extraction under the permutation ----------------------------------
template<int W>
__device__ __forceinline__ void fill_ev(float (&ev)[8], float wht,
                                        const float (&E)[3]) {
    if constexpr (W < 8) {
        constexpr int P = wposf(W);
        if constexpr (P >= 3)
            ev[W] = __shfl_sync(0xffffffffu, wht, 1 << (P - 3));
        else
            ev[W] = E[P];
        fill_ev<W + 1>(ev, wht, E);
    }
}

// ---------------- kernel 1: statevector sim + MLP layer 1 ------------------
__global__ __launch_bounds__(256)
void qsim_kernel(const float* __restrict__ x,
                 const float* __restrict__ ry_theta,
                 const float* __restrict__ rand_params,
                 const float* __restrict__ W1,
                 const float* __restrict__ b1)
{
    __shared__ float gc[28], gs[28];
    __shared__ float W1t[8 * 64];
    __shared__ float b1s[64];
    __shared__ float Hs[64][9];           // pad 9: conflict-free scatter

    const int tid = threadIdx.x;
    if (tid < 28) {
        float th = (tid < 20) ? rand_params[tid] : ry_theta[tid - 20];
        float s, c;
        sincosf(0.5f * th, &s, &c);
        gc[tid] = c;
        gs[tid] = s;                      // CNOT slots unused by do_gate
    }
    if (tid < 64) b1s[tid] = b1[tid];
    for (int i = tid; i < 512; i += 256) {
        int j = i >> 3, w = i & 7;
        W1t[w * 64 + j] = W1[i];
    }
    __syncthreads();

    const int lane  = tid & 31;
    const int wid   = tid >> 5;
    const int token0 = blockIdx.x * 8;
    const int token  = token0 + wid;

    // ---- initial product state from the 8 input features ----
    const float* xf = x + (size_t)token * 512;
    float cw[8], sw[8];
#pragma unroll
    for (int w = 0; w < 8; w++) {
        float f = __ldg(xf + w);
        __sincosf(0.5f * f, &sw[w], &cw[w]);
    }
    float re[8], im[8];
    {
        const float lf = lane_init<0>(cw, sw, lane);
        set_init<0>(re, im, lf, cw, sw);
    }

    // ---- 20 random gates + 8 final RY gates (fully unrolled) ----
    run_gates<0>(re, im, gc, gs, lane);

    // ---- probs -> per-lane partials ----
    float S = 0.f;
    float E[3] = {0.f, 0.f, 0.f};
#pragma unroll
    for (int r = 0; r < 8; r++) {
        float p = re[r] * re[r] + im[r] * im[r];
        S += p;
        E[0] += (r & 1) ? -p : p;
        E[1] += (r & 2) ? -p : p;
        E[2] += (r & 4) ? -p : p;
    }
    // Walsh-Hadamard over lanes: lane j ends with F(j)=sum_i (-1)^{pc(i&j)} S_i
    float wht = S;
#pragma unroll
    for (int m = 16; m >= 1; m >>= 1) {
        float t = __shfl_xor_sync(0xffffffffu, wht, m);
        wht = (lane & m) ? (t - wht) : (t + wht);
    }
    // plain butterflies for the 3 register-bit expectations
#pragma unroll
    for (int e = 0; e < 3; e++) {
        float v = E[e];
#pragma unroll
        for (int m = 16; m >= 1; m >>= 1) v += __shfl_xor_sync(0xffffffffu, v, m);
        E[e] = v;
    }
    float ev[8];
    fill_ev<0>(ev, wht, E);

    // ---- MLP layer 1: h = relu(ev @ W1^T + b1), staged to smem ----
#pragma unroll
    for (int half = 0; half < 2; half++) {
        const int j = lane + half * 32;
        float acc = b1s[j];
#pragma unroll
        for (int w = 0; w < 8; w++) acc = fmaf(ev[w], W1t[w * 64 + j], acc);
        Hs[j][wid] = fmaxf(acc, 0.f);
    }
    __syncthreads();

    // ---- bf16 hi/lo split writeout: g_A[m][0:64]=hi, [64:128]=lo ----
#pragma unroll
    for (int it = 0; it < 2; it++) {
        const int idx = it * 256 + tid;           // 512 h-values per block
        const int tok = idx >> 6, j = idx & 63;
        float h = Hs[j][tok];
        __nv_bfloat16 hi = __float2bfloat16(h);
        __nv_bfloat16 lo = __float2bfloat16(h - __bfloat162float(hi));
        __nv_bfloat16* row = g_A + (size_t)(token0 + tok) * 128;
        row[j]      = hi;
        row[64 + j] = lo;
    }
}

// ---------------- kernel 2: out = H @ W2^T + b2  (split-bf16 HMMA) ---------
// M=16384, N=512, K=64 fp32 ->  bf16 hi/lo, 3 K-block products:
//   blk0: A=hi, B=whi   blk1: A=lo, B=whi   blk2: A=hi, B=wlo
// BM=128, BN=64, 256 threads (8 warps as 4m x 2n, each warp 32m x 32n).
#define PITCH 272   // smem row pitch in bytes (136 bf16): conflict-free ldmatrix
__global__ __launch_bounds__(256)
void mlp2_kernel(const float* __restrict__ W2,
                 const float* __restrict__ b2,
                 float* __restrict__ out)
{
    extern __shared__ char smem[];
    char* As = smem;                  // [128 rows][PITCH]  bf16 (hi|lo)
    char* Bs = smem + 128 * PITCH;    // [64 rows][PITCH]   bf16 (whi|wlo)

    const int tid = threadIdx.x;
    const int m0 = blockIdx.y * 128;
    const int n0 = blockIdx.x * 64;

    // ---- load A tile (bf16, 128 rows x 256B) ----
#pragma unroll
    for (int it = 0; it < 8; it++) {
        const int c = it * 256 + tid;             // 2048 x 16B chunks
        const int row = c >> 4, ch = c & 15;
        uint4 v = *(const uint4*)((const char*)g_A + (size_t)(m0 + row) * 256 + ch * 16);
        *(uint4*)(As + row * PITCH + ch * 16) = v;
    }
    // ---- load W2 tile (f32) and split to bf16 hi|lo in smem ----
#pragma unroll
    for (int it = 0; it < 8; it++) {
        const int c = it * 256 + tid;             // 2048 x float2
        const int n = c >> 5, kk = c & 31;        // k pair index
        float2 v = *(const float2*)(W2 + (size_t)(n0 + n) * 64 + kk * 2);
        __nv_bfloat16 h0 = __float2bfloat16(v.x);
        __nv_bfloat16 h1 = __float2bfloat16(v.y);
        __nv_bfloat16 l0 = __float2bfloat16(v.x - __bfloat162float(h0));
        __nv_bfloat16 l1 = __float2bfloat16(v.y - __bfloat162float(h1));
        *(__nv_bfloat162*)(Bs + n * PITCH + kk * 4)       = __nv_bfloat162(h0, h1);
        *(__nv_bfloat162*)(Bs + n * PITCH + 128 + kk * 4) = __nv_bfloat162(l0, l1);
    }
    __syncthreads();

    const int lane = tid & 31;
    const int wid  = tid >> 5;
    const int wm = (wid & 3) * 32;    // warp m-origin within tile
    const int wn = (wid >> 2) * 32;   // warp n-origin within tile

    const uint32_t aBase = smem_u32(As);
    const uint32_t bBase = smem_u32(Bs);
    uint32_t aRow[2], bRow[4];
#pragma unroll
    for (int mt = 0; mt < 2; mt++)
        aRow[mt] = aBase + (wm + mt * 16 + (lane & 15)) * PITCH + (lane >> 4) * 16;
#pragma unroll
    for (int nt = 0; nt < 4; nt++)
        bRow[nt] = bBase + (wn + nt * 8 + (lane & 7)) * PITCH + ((lane >> 3) & 1) * 16;

    float acc[2][4][4];
#pragma unroll
    for (int mt = 0; mt < 2; mt++)
#pragma unroll
        for (int nt = 0; nt < 4; nt++)
#pragma unroll
            for (int i = 0; i < 4; i++) acc[mt][nt][i] = 0.f;

#pragma unroll
    for (int blk = 0; blk < 3; blk++) {
        const int ka = (blk == 1) ? 128 : 0;      // A byte offset: hi,lo,hi
        const int kb = (blk == 2) ? 128 : 0;      // B byte offset: whi,whi,wlo
#pragma unroll
        for (int ks = 0; ks < 4; ks++) {
            const int koa = ka + ks * 32;          // 16 bf16 = 32 bytes
            const int kob = kb + ks * 32;
            uint32_t a[2][4], b[4][2];
#pragma unroll
            for (int mt = 0; mt < 2; mt++) ldsm4(a[mt], aRow[mt] + koa);
#pragma unroll
            for (int nt = 0; nt < 4; nt++) ldsm2(b[nt], bRow[nt] + kob);
#pragma unroll
            for (int mt = 0; mt < 2; mt++)
#pragma unroll
                for (int nt = 0; nt < 4; nt++)
                    mma_bf16(acc[mt][nt], a[mt], b[nt]);
        }
    }

    // ---- epilogue: add bias, write fp32 ----
#pragma unroll
    for (int nt = 0; nt < 4; nt++) {
        const int n = n0 + wn + nt * 8 + (lane & 3) * 2;
        const float2 bb = *(const float2*)(b2 + n);
#pragma unroll
        for (int mt = 0; mt < 2; mt++) {
            const int r0 = m0 + wm + mt * 16 + (lane >> 2);
            const float* c = acc[mt][nt];
            float2 o0 = {c[0] + bb.x, c[1] + bb.y};
            float2 o1 = {c[2] + bb.x, c[3] + bb.y};
            *(float2*)(out + (size_t)r0 * 512 + n)       = o0;
            *(float2*)(out + (size_t)(r0 + 8) * 512 + n) = o1;
        }
    }
}

// ---------------- entry point ----------------------------------------------
extern "C" void kernel_launch(void* const* d_in, const int* in_sizes, int n_in,
                              void* d_out, int out_size)
{
    const float* x  = (const float*)d_in[0];
    const float* ry = (const float*)d_in[1];
    const float* rp = (const float*)d_in[2];
    const float* W1 = (const float*)d_in[3];
    const float* b1 = (const float*)d_in[4];
    const float* W2 = (const float*)d_in[5];
    const float* b2 = (const float*)d_in[6];
    float* out = (float*)d_out;

    const int tokens = in_sizes[0] / 512;      // 16384

    // single launch: grid 2048 -> full occupancy (R15's 4-way split capped
    // oe at ceil(512/148)=3.46 CTAs/SM and added 4 launch tails)
    qsim_kernel<<<tokens / 8, 256>>>(x, ry, rp, W1, b1);

    const int smem2 = (128 + 64) * PITCH;      // 52224 B
    cudaFuncSetAttribute(mlp2_kernel,
                         cudaFuncAttributeMaxDynamicSharedMemorySize, smem2);
    dim3 g2(512 / 64, tokens / 128);
    mlp2_kernel<<<g2, 256, smem2>>>(W2, b2, out);
}